// round 1
// baseline (speedup 1.0000x reference)
#include <cuda_runtime.h>
#include <cuda_bf16.h>

// Problem constants (shapes are fixed by the reference)
#define NN      10000
#define EE      640000
#define TOT_E   (EE + NN)      // edges + self loops
#define IN_FT   512
#define OUT_FT  128

// ---------------- device scratch (no allocation allowed) ----------------
__device__ float g_h[NN * OUT_FT];        // h = seq @ W_comb^T
__device__ float g_wc[OUT_FT * IN_FT];    // W_comb = W_gat @ W_fc
__device__ float g_as[NN];                // h @ att_src
__device__ float g_ad[NN];                // h @ att_dst
__device__ int   g_cnt[NN];               // per-dst edge counts
__device__ int   g_rowptr[NN + 1];        // CSR row pointers (by dst)
__device__ int   g_fill[NN];              // scatter cursors
__device__ int   g_csr[TOT_E];            // src node id per CSR slot
__device__ int   g_flag;                  // 1 = edge_index is int32, 0 = int64

// ---------------- helpers ----------------
__device__ __forceinline__ int2 load_edge(const void* p, int e, int E) {
    if (g_flag) {
        const int* q = (const int*)p;
        return make_int2(q[e], q[E + e]);
    } else {
        const long long* q = (const long long*)p;
        return make_int2((int)q[e], (int)q[E + e]);
    }
}

// ---------------- kernels ----------------
__global__ void zero_kernel(int n) {
    int i = blockIdx.x * blockDim.x + threadIdx.x;
    if (i < n) g_cnt[i] = 0;
    if (i == 0) g_flag = 0;
}

// Detect int32 vs int64 edge_index: if data is int64, every odd 32-bit word
// (high half of a value < 2^31) is zero. If int32, odd words are random node
// ids (certainly not all zero over 1024 samples).
__global__ void detect_kernel(const int* p, int E) {
    int i = blockIdx.x * blockDim.x + threadIdx.x;
    if (i < 1024 && i < E) {
        if (p[2 * i + 1] != 0) atomicOr(&g_flag, 1);
    }
}

// W_comb[o][k] = sum_m W_gat[o][m] * W_fc[m][k];  grid=(OUT_FT), block=(IN_FT)
__global__ void wcomb_kernel(const float* __restrict__ Wgat,
                             const float* __restrict__ Wfc) {
    __shared__ float wrow[OUT_FT];
    int o = blockIdx.x;
    int k = threadIdx.x;
    if (k < OUT_FT) wrow[k] = Wgat[o * OUT_FT + k];
    __syncthreads();
    float acc = 0.f;
#pragma unroll 8
    for (int m = 0; m < OUT_FT; m++)
        acc += wrow[m] * Wfc[m * IN_FT + k];
    g_wc[o * IN_FT + k] = acc;
}

// h = seq @ W_comb^T.  BM=32 rows, BN=128 (all cols), BK=32. 256 threads.
// Shared tiles stored k-major so compute loads are vectorized.
__global__ void gemm_h_kernel(const float* __restrict__ seq, int n) {
    __shared__ float As[32][34];    // As[kk][row], stride 34 keeps 8B alignment
    __shared__ float Bs[32][132];   // Bs[kk][col], stride 132 keeps 16B alignment

    int bm  = blockIdx.x * 32;
    int tid = threadIdx.x;
    int ty  = tid >> 4;          // 0..15 -> 2 rows each
    int tx  = tid & 15;          // 0..15 -> 8 cols each

    float acc[2][8];
#pragma unroll
    for (int i = 0; i < 2; i++)
#pragma unroll
        for (int j = 0; j < 8; j++) acc[i][j] = 0.f;

    for (int k0 = 0; k0 < IN_FT; k0 += 32) {
        // load seq tile 32x32 (row-major in gmem, k-major in smem)
        for (int l = tid; l < 32 * 32; l += 256) {
            int r = l >> 5, c = l & 31;
            int row = bm + r;
            As[c][r] = (row < n) ? seq[row * IN_FT + k0 + c] : 0.f;
        }
        // load W_comb tile 128x32
        for (int l = tid; l < 128 * 32; l += 256) {
            int r = l >> 5, c = l & 31;
            Bs[c][r] = g_wc[r * IN_FT + k0 + c];
        }
        __syncthreads();

#pragma unroll
        for (int kk = 0; kk < 32; kk++) {
            float2 a2 = *(const float2*)&As[kk][ty * 2];
            float4 b0 = *(const float4*)&Bs[kk][tx * 8];
            float4 b1 = *(const float4*)&Bs[kk][tx * 8 + 4];
            float b[8] = {b0.x, b0.y, b0.z, b0.w, b1.x, b1.y, b1.z, b1.w};
            float a[2] = {a2.x, a2.y};
#pragma unroll
            for (int i = 0; i < 2; i++)
#pragma unroll
                for (int j = 0; j < 8; j++)
                    acc[i][j] += a[i] * b[j];
        }
        __syncthreads();
    }

#pragma unroll
    for (int i = 0; i < 2; i++) {
        int row = bm + ty * 2 + i;
        if (row < n) {
            float4 v0 = make_float4(acc[i][0], acc[i][1], acc[i][2], acc[i][3]);
            float4 v1 = make_float4(acc[i][4], acc[i][5], acc[i][6], acc[i][7]);
            *(float4*)&g_h[row * OUT_FT + tx * 8]     = v0;
            *(float4*)&g_h[row * OUT_FT + tx * 8 + 4] = v1;
        }
    }
}

// a_s[n] = h[n] . att_src,  a_d[n] = h[n] . att_dst  (one warp per node)
__global__ void asad_kernel(const float* __restrict__ att_s,
                            const float* __restrict__ att_d, int n) {
    int gw   = (blockIdx.x * blockDim.x + threadIdx.x) >> 5;
    int lane = threadIdx.x & 31;
    if (gw >= n) return;
    float4 hv = *(const float4*)&g_h[gw * OUT_FT + lane * 4];
    float4 s4 = *(const float4*)&att_s[lane * 4];
    float4 d4 = *(const float4*)&att_d[lane * 4];
    float vs = hv.x * s4.x + hv.y * s4.y + hv.z * s4.z + hv.w * s4.w;
    float vd = hv.x * d4.x + hv.y * d4.y + hv.z * d4.z + hv.w * d4.w;
#pragma unroll
    for (int o = 16; o > 0; o >>= 1) {
        vs += __shfl_xor_sync(0xffffffffu, vs, o);
        vd += __shfl_xor_sync(0xffffffffu, vd, o);
    }
    if (lane == 0) { g_as[gw] = vs; g_ad[gw] = vd; }
}

__global__ void count_kernel(const void* eidx, int E, int n) {
    int i = blockIdx.x * blockDim.x + threadIdx.x;
    int tot = E + n;
    if (i >= tot) return;
    int d;
    if (i < E) { int2 sd = load_edge(eidx, i, E); d = sd.y; }
    else        d = i - E;
    atomicAdd(&g_cnt[d], 1);
}

// Single-block exclusive scan over g_cnt -> g_rowptr / g_fill
__global__ void scan_kernel(int n) {
    __shared__ int part[1024];
    int tid  = threadIdx.x;
    int per  = (n + 1023) / 1024;
    if (per > 16) per = 16;   // n is 10000; per=10
    int base = tid * per;
    int loc[16];
    int sum = 0;
    for (int j = 0; j < per; j++) {
        int idx = base + j;
        int v = (idx < n) ? g_cnt[idx] : 0;
        loc[j] = sum;
        sum += v;
    }
    part[tid] = sum;
    __syncthreads();
    // Hillis-Steele inclusive scan
    for (int off = 1; off < 1024; off <<= 1) {
        int v = (tid >= off) ? part[tid - off] : 0;
        __syncthreads();
        part[tid] += v;
        __syncthreads();
    }
    int excl = (tid == 0) ? 0 : part[tid - 1];
    for (int j = 0; j < per; j++) {
        int idx = base + j;
        if (idx < n) {
            int rp = excl + loc[j];
            g_rowptr[idx] = rp;
            g_fill[idx]   = rp;
        }
    }
    if (tid == 1023) g_rowptr[n] = part[1023];
}

__global__ void scatter_kernel(const void* eidx, int E, int n) {
    int i = blockIdx.x * blockDim.x + threadIdx.x;
    int tot = E + n;
    if (i >= tot) return;
    int s, d;
    if (i < E) { int2 sd = load_edge(eidx, i, E); s = sd.x; d = sd.y; }
    else       { s = d = i - E; }
    int pos = atomicAdd(&g_fill[d], 1);
    g_csr[pos] = s;
}

// One block (128 threads) per destination node: segment softmax + weighted sum
__global__ void aggregate_kernel(const float* __restrict__ gat_bias,
                                 const float* __restrict__ bias,
                                 const float* __restrict__ prelu_a,
                                 float* __restrict__ out, int n) {
    int d = blockIdx.x;
    if (d >= n) return;
    int tid   = threadIdx.x;   // = feature index, 0..127
    int start = g_rowptr[d];
    int end   = g_rowptr[d + 1];
    float ad  = g_ad[d];

    __shared__ float red[4];
    __shared__ float p_sh[128];
    __shared__ int   s_sh[128];

    // pass 1: segment max (self-loop guarantees >= 1 edge)
    float lm = -1e30f;
    for (int i = start + tid; i < end; i += 128) {
        float e = g_as[g_csr[i]] + ad;
        e = (e >= 0.f) ? e : 0.2f * e;
        lm = fmaxf(lm, e);
    }
#pragma unroll
    for (int o = 16; o > 0; o >>= 1)
        lm = fmaxf(lm, __shfl_xor_sync(0xffffffffu, lm, o));
    if ((tid & 31) == 0) red[tid >> 5] = lm;
    __syncthreads();
    float m = fmaxf(fmaxf(red[0], red[1]), fmaxf(red[2], red[3]));
    __syncthreads();

    // pass 2: denom
    float ls = 0.f;
    for (int i = start + tid; i < end; i += 128) {
        float e = g_as[g_csr[i]] + ad;
        e = (e >= 0.f) ? e : 0.2f * e;
        ls += __expf(e - m);
    }
#pragma unroll
    for (int o = 16; o > 0; o >>= 1)
        ls += __shfl_xor_sync(0xffffffffu, ls, o);
    if ((tid & 31) == 0) red[tid >> 5] = ls;
    __syncthreads();
    float denom = red[0] + red[1] + red[2] + red[3];
    __syncthreads();

    // pass 3: weighted accumulate of h[src] rows (L2-resident gathers)
    float acc = 0.f;
    for (int c = start; c < end; c += 128) {
        int i = c + tid;
        if (i < end) {
            int s = g_csr[i];
            float e = g_as[s] + ad;
            e = (e >= 0.f) ? e : 0.2f * e;
            p_sh[tid] = __expf(e - m);
            s_sh[tid] = s;
        }
        __syncthreads();
        int len = min(128, end - c);
#pragma unroll 4
        for (int j = 0; j < len; j++)
            acc += p_sh[j] * g_h[s_sh[j] * OUT_FT + tid];
        __syncthreads();
    }

    float o_ = acc / (denom + 1e-16f) + gat_bias[tid] + bias[tid];
    float a  = prelu_a[0];
    out[d * OUT_FT + tid] = (o_ >= 0.f) ? o_ : a * o_;
}

// ---------------- launch ----------------
extern "C" void kernel_launch(void* const* d_in, const int* in_sizes, int n_in,
                              void* d_out, int out_size) {
    const float* seq      = (const float*)d_in[0];
    const void*  eidx     = d_in[1];
    const float* Wfc      = (const float*)d_in[2];
    const float* Wgat     = (const float*)d_in[3];
    const float* att_src  = (const float*)d_in[4];
    const float* att_dst  = (const float*)d_in[5];
    const float* gat_bias = (const float*)d_in[6];
    const float* bias     = (const float*)d_in[7];
    const float* prelu_a  = (const float*)d_in[8];
    float* out = (float*)d_out;

    int n = in_sizes[0] / IN_FT;     // 10000
    int E = in_sizes[1] / 2;         // 640000 (element count same for i32/i64)
    int tot = E + n;

    zero_kernel<<<(n + 255) / 256, 256>>>(n);
    detect_kernel<<<4, 256>>>((const int*)eidx, E);
    wcomb_kernel<<<OUT_FT, IN_FT>>>(Wgat, Wfc);
    gemm_h_kernel<<<(n + 31) / 32, 256>>>(seq, n);
    asad_kernel<<<(n * 32 + 255) / 256, 256>>>(att_src, att_dst, n);
    count_kernel<<<(tot + 255) / 256, 256>>>(eidx, E, n);
    scan_kernel<<<1, 1024>>>(n);
    scatter_kernel<<<(tot + 255) / 256, 256>>>(eidx, E, n);
    aggregate_kernel<<<n, 128>>>(gat_bias, bias, prelu_a, out, n);
}

// round 2
// speedup vs baseline: 1.2927x; 1.2927x over previous
#include <cuda_runtime.h>
#include <cuda_bf16.h>

// Problem constants (shapes are fixed by the reference)
#define NN      10000
#define EE      640000
#define TOT_E   (EE + NN)      // edges + self loops
#define IN_FT   512
#define OUT_FT  128

#define BM 64
#define BN 128
#define BK 32
#define NKT (IN_FT / BK)       // 16 k-tiles

// ---------------- device scratch (no allocation allowed) ----------------
__device__ float g_h[NN * OUT_FT];         // h = seq @ W_comb^T
__device__ float g_wcT[IN_FT * OUT_FT];    // W_comb transposed: [k][o]
__device__ float g_as[NN];                 // h @ att_src
__device__ float g_ad[NN];                 // h @ att_dst
__device__ int   g_cnt[NN];                // per-dst edge counts
__device__ int   g_rowptr[NN + 1];         // CSR row pointers (by dst)
__device__ int   g_fill[NN];               // scatter cursors
__device__ int   g_csr[TOT_E];             // src node id per CSR slot
__device__ int   g_flag;                   // 1 = edge_index is int32, 0 = int64

// ---------------- helpers ----------------
__device__ __forceinline__ int2 load_edge(const void* p, int e, int E) {
    if (g_flag) {
        const int* q = (const int*)p;
        return make_int2(q[e], q[E + e]);
    } else {
        const long long* q = (const long long*)p;
        return make_int2((int)q[e], (int)q[E + e]);
    }
}

// ---------------- kernels ----------------
__global__ void zero_kernel(int n) {
    int i = blockIdx.x * blockDim.x + threadIdx.x;
    if (i < n) g_cnt[i] = 0;
    if (i == 0) g_flag = 0;
}

// Detect int32 vs int64 edge_index: for int64 node ids < 2^31 the high words
// are all zero; for int32 they contain random node ids.
__global__ void detect_kernel(const int* p, int E) {
    int i = blockIdx.x * blockDim.x + threadIdx.x;
    if (i < 1024 && i < E) {
        if (p[2 * i + 1] != 0) atomicOr(&g_flag, 1);
    }
}

// W_combT[k][o] = sum_m W_gat[o][m] * W_fc[m][k];  grid=(OUT_FT), block=(IN_FT)
__global__ void wcomb_kernel(const float* __restrict__ Wgat,
                             const float* __restrict__ Wfc) {
    __shared__ float wrow[OUT_FT];
    int o = blockIdx.x;
    int k = threadIdx.x;
    if (k < OUT_FT) wrow[k] = Wgat[o * OUT_FT + k];
    __syncthreads();
    float acc = 0.f;
#pragma unroll 8
    for (int m = 0; m < OUT_FT; m++)
        acc += wrow[m] * Wfc[m * IN_FT + k];
    g_wcT[k * OUT_FT + o] = acc;          // transposed store
}

// h = seq @ W_comb^T.  BM=64 x BN=128 x BK=32, 256 threads, 4x8 microtile,
// register-prefetch double buffering. FMA-bound by design.
__global__ __launch_bounds__(256, 2) void gemm_h_kernel(const float* __restrict__ seq, int n) {
    __shared__ float As[BM][BK + 1];   // row-major, pitch 33 (conflict-free)
    __shared__ float Bs[BK][BN];       // k-major, aligned for LDS.128

    int bm  = blockIdx.x * BM;
    int tid = threadIdx.x;
    int ty  = tid >> 4;          // 0..15 -> 4 rows each
    int tx  = tid & 15;          // 0..15 -> 8 cols each
    int r0  = ty * 4;

    float acc[4][8];
#pragma unroll
    for (int i = 0; i < 4; i++)
#pragma unroll
        for (int j = 0; j < 8; j++) acc[i][j] = 0.f;

    float4 pa[2], pb[4];

    // --- tile load helpers (fully coalesced LDG.128) ---
    auto loadA = [&](int k0) {
#pragma unroll
        for (int i = 0; i < 2; i++) {
            int idx = tid + i * 256;          // 0..511
            int r = idx >> 3, c4 = (idx & 7) << 2;
            int row = bm + r;
            pa[i] = (row < n) ? *(const float4*)&seq[row * IN_FT + k0 + c4]
                              : make_float4(0.f, 0.f, 0.f, 0.f);
        }
    };
    auto loadB = [&](int k0) {
#pragma unroll
        for (int i = 0; i < 4; i++) {
            int idx = tid + i * 256;          // 0..1023
            int kk = idx >> 5, o4 = (idx & 31) << 2;
            pb[i] = *(const float4*)&g_wcT[(k0 + kk) * OUT_FT + o4];
        }
    };
    auto storeT = [&]() {
#pragma unroll
        for (int i = 0; i < 2; i++) {
            int idx = tid + i * 256;
            int r = idx >> 3, c4 = (idx & 7) << 2;
            As[r][c4 + 0] = pa[i].x;          // scalar STS, conflict-free
            As[r][c4 + 1] = pa[i].y;
            As[r][c4 + 2] = pa[i].z;
            As[r][c4 + 3] = pa[i].w;
        }
#pragma unroll
        for (int i = 0; i < 4; i++) {
            int idx = tid + i * 256;
            int kk = idx >> 5, o4 = (idx & 31) << 2;
            *(float4*)&Bs[kk][o4] = pb[i];    // aligned STS.128, conflict-free
        }
    };

    loadA(0); loadB(0);
    storeT();
    __syncthreads();

    for (int kt = 0; kt < NKT; kt++) {
        if (kt + 1 < NKT) { loadA((kt + 1) * BK); loadB((kt + 1) * BK); }

#pragma unroll
        for (int kk = 0; kk < BK; kk++) {
            float a[4];
#pragma unroll
            for (int i = 0; i < 4; i++) a[i] = As[r0 + i][kk];
            float4 b0 = *(const float4*)&Bs[kk][tx * 8];
            float4 b1 = *(const float4*)&Bs[kk][tx * 8 + 4];
            float b[8] = {b0.x, b0.y, b0.z, b0.w, b1.x, b1.y, b1.z, b1.w};
#pragma unroll
            for (int i = 0; i < 4; i++)
#pragma unroll
                for (int j = 0; j < 8; j++)
                    acc[i][j] += a[i] * b[j];
        }
        __syncthreads();
        if (kt + 1 < NKT) {
            storeT();
            __syncthreads();
        }
    }

#pragma unroll
    for (int i = 0; i < 4; i++) {
        int row = bm + r0 + i;
        if (row < n) {
            float4 v0 = make_float4(acc[i][0], acc[i][1], acc[i][2], acc[i][3]);
            float4 v1 = make_float4(acc[i][4], acc[i][5], acc[i][6], acc[i][7]);
            *(float4*)&g_h[row * OUT_FT + tx * 8]     = v0;
            *(float4*)&g_h[row * OUT_FT + tx * 8 + 4] = v1;
        }
    }
}

// a_s[n] = h[n] . att_src,  a_d[n] = h[n] . att_dst  (one warp per node)
__global__ void asad_kernel(const float* __restrict__ att_s,
                            const float* __restrict__ att_d, int n) {
    int gw   = (blockIdx.x * blockDim.x + threadIdx.x) >> 5;
    int lane = threadIdx.x & 31;
    if (gw >= n) return;
    float4 hv = *(const float4*)&g_h[gw * OUT_FT + lane * 4];
    float4 s4 = *(const float4*)&att_s[lane * 4];
    float4 d4 = *(const float4*)&att_d[lane * 4];
    float vs = hv.x * s4.x + hv.y * s4.y + hv.z * s4.z + hv.w * s4.w;
    float vd = hv.x * d4.x + hv.y * d4.y + hv.z * d4.z + hv.w * d4.w;
#pragma unroll
    for (int o = 16; o > 0; o >>= 1) {
        vs += __shfl_xor_sync(0xffffffffu, vs, o);
        vd += __shfl_xor_sync(0xffffffffu, vd, o);
    }
    if (lane == 0) { g_as[gw] = vs; g_ad[gw] = vd; }
}

__global__ void count_kernel(const void* eidx, int E, int n) {
    int i = blockIdx.x * blockDim.x + threadIdx.x;
    int tot = E + n;
    if (i >= tot) return;
    int d;
    if (i < E) { int2 sd = load_edge(eidx, i, E); d = sd.y; }
    else        d = i - E;
    atomicAdd(&g_cnt[d], 1);
}

// Single-block exclusive scan over g_cnt -> g_rowptr / g_fill
__global__ void scan_kernel(int n) {
    __shared__ int part[1024];
    int tid  = threadIdx.x;
    int per  = (n + 1023) / 1024;
    if (per > 16) per = 16;
    int base = tid * per;
    int loc[16];
    int sum = 0;
    for (int j = 0; j < per; j++) {
        int idx = base + j;
        int v = (idx < n) ? g_cnt[idx] : 0;
        loc[j] = sum;
        sum += v;
    }
    part[tid] = sum;
    __syncthreads();
    for (int off = 1; off < 1024; off <<= 1) {
        int v = (tid >= off) ? part[tid - off] : 0;
        __syncthreads();
        part[tid] += v;
        __syncthreads();
    }
    int excl = (tid == 0) ? 0 : part[tid - 1];
    for (int j = 0; j < per; j++) {
        int idx = base + j;
        if (idx < n) {
            int rp = excl + loc[j];
            g_rowptr[idx] = rp;
            g_fill[idx]   = rp;
        }
    }
    if (tid == 1023) g_rowptr[n] = part[1023];
}

__global__ void scatter_kernel(const void* eidx, int E, int n) {
    int i = blockIdx.x * blockDim.x + threadIdx.x;
    int tot = E + n;
    if (i >= tot) return;
    int s, d;
    if (i < E) { int2 sd = load_edge(eidx, i, E); s = sd.x; d = sd.y; }
    else       { s = d = i - E; }
    int pos = atomicAdd(&g_fill[d], 1);
    g_csr[pos] = s;
}

// One block (128 threads) per destination node: segment softmax + weighted sum
__global__ void aggregate_kernel(const float* __restrict__ gat_bias,
                                 const float* __restrict__ bias,
                                 const float* __restrict__ prelu_a,
                                 float* __restrict__ out, int n) {
    int d = blockIdx.x;
    if (d >= n) return;
    int tid   = threadIdx.x;   // = feature index, 0..127
    int start = g_rowptr[d];
    int end   = g_rowptr[d + 1];
    float ad  = g_ad[d];

    __shared__ float red[4];
    __shared__ float p_sh[128];
    __shared__ int   s_sh[128];

    // pass 1: segment max (self-loop guarantees >= 1 edge)
    float lm = -1e30f;
    for (int i = start + tid; i < end; i += 128) {
        float e = g_as[g_csr[i]] + ad;
        e = (e >= 0.f) ? e : 0.2f * e;
        lm = fmaxf(lm, e);
    }
#pragma unroll
    for (int o = 16; o > 0; o >>= 1)
        lm = fmaxf(lm, __shfl_xor_sync(0xffffffffu, lm, o));
    if ((tid & 31) == 0) red[tid >> 5] = lm;
    __syncthreads();
    float m = fmaxf(fmaxf(red[0], red[1]), fmaxf(red[2], red[3]));
    __syncthreads();

    // pass 2: denom
    float ls = 0.f;
    for (int i = start + tid; i < end; i += 128) {
        float e = g_as[g_csr[i]] + ad;
        e = (e >= 0.f) ? e : 0.2f * e;
        ls += __expf(e - m);
    }
#pragma unroll
    for (int o = 16; o > 0; o >>= 1)
        ls += __shfl_xor_sync(0xffffffffu, ls, o);
    if ((tid & 31) == 0) red[tid >> 5] = ls;
    __syncthreads();
    float denom = red[0] + red[1] + red[2] + red[3];
    __syncthreads();

    // pass 3: weighted accumulate of h[src] rows (L2-resident gathers)
    float acc = 0.f;
    for (int c = start; c < end; c += 128) {
        int i = c + tid;
        if (i < end) {
            int s = g_csr[i];
            float e = g_as[s] + ad;
            e = (e >= 0.f) ? e : 0.2f * e;
            p_sh[tid] = __expf(e - m);
            s_sh[tid] = s;
        }
        __syncthreads();
        int len = min(128, end - c);
#pragma unroll 4
        for (int j = 0; j < len; j++)
            acc += p_sh[j] * g_h[s_sh[j] * OUT_FT + tid];
        __syncthreads();
    }

    float o_ = acc / (denom + 1e-16f) + gat_bias[tid] + bias[tid];
    float a  = prelu_a[0];
    out[d * OUT_FT + tid] = (o_ >= 0.f) ? o_ : a * o_;
}

// ---------------- launch ----------------
extern "C" void kernel_launch(void* const* d_in, const int* in_sizes, int n_in,
                              void* d_out, int out_size) {
    const float* seq      = (const float*)d_in[0];
    const void*  eidx     = d_in[1];
    const float* Wfc      = (const float*)d_in[2];
    const float* Wgat     = (const float*)d_in[3];
    const float* att_src  = (const float*)d_in[4];
    const float* att_dst  = (const float*)d_in[5];
    const float* gat_bias = (const float*)d_in[6];
    const float* bias     = (const float*)d_in[7];
    const float* prelu_a  = (const float*)d_in[8];
    float* out = (float*)d_out;

    int n = in_sizes[0] / IN_FT;     // 10000
    int E = in_sizes[1] / 2;         // 640000
    int tot = E + n;

    zero_kernel<<<(n + 255) / 256, 256>>>(n);
    detect_kernel<<<4, 256>>>((const int*)eidx, E);
    wcomb_kernel<<<OUT_FT, IN_FT>>>(Wgat, Wfc);
    gemm_h_kernel<<<(n + BM - 1) / BM, 256>>>(seq, n);
    asad_kernel<<<(n * 32 + 255) / 256, 256>>>(att_src, att_dst, n);
    count_kernel<<<(tot + 255) / 256, 256>>>(eidx, E, n);
    scan_kernel<<<1, 1024>>>(n);
    scatter_kernel<<<(tot + 255) / 256, 256>>>(eidx, E, n);
    aggregate_kernel<<<n, 128>>>(gat_bias, bias, prelu_a, out, n);
}

// round 3
// speedup vs baseline: 1.8963x; 1.4670x over previous
#include <cuda_runtime.h>
#include <cuda_bf16.h>
#include <cstdint>

// Problem constants (shapes are fixed by the reference)
#define NN      10000
#define EE      640000
#define TOT_E   (EE + NN)      // edges + self loops
#define IN_FT   512
#define OUT_FT  128

#define BM 32
#define BK 32
#define NKT (IN_FT / BK)       // 16 k-tiles
#define MAXD 512

// ---------------- device scratch (no allocation allowed) ----------------
__device__ float g_h[NN * OUT_FT];         // h = seq @ W_comb^T
__device__ float g_wcT[IN_FT * OUT_FT];    // W_comb transposed: [k][o]
__device__ float g_as[NN];                 // h @ att_src
__device__ float g_ad[NN];                 // h @ att_dst
__device__ int   g_cnt[NN];                // per-dst edge counts
__device__ int   g_rowptr[NN + 1];         // CSR row pointers (by dst)
__device__ int   g_fill[NN];               // scatter cursors
__device__ int   g_csr[TOT_E];             // src node id per CSR slot
__device__ int   g_src[TOT_E];             // decoded src
__device__ int   g_dst[TOT_E];             // decoded dst
__device__ int   g_flag;                   // 1 = edge_index is int32, 0 = int64

// ---------------- helpers ----------------
__device__ __forceinline__ int2 load_edge(const void* p, int e, int E) {
    if (g_flag) {
        const int* q = (const int*)p;
        return make_int2(q[e], q[E + e]);
    } else {
        const long long* q = (const long long*)p;
        return make_int2((int)q[e], (int)q[E + e]);
    }
}

__device__ __forceinline__ void cp16(void* dst, const void* src) {
    uint32_t d = (uint32_t)__cvta_generic_to_shared(dst);
    asm volatile("cp.async.cg.shared.global [%0], [%1], 16;\n" :: "r"(d), "l"(src));
}
__device__ __forceinline__ void cp_commit() {
    asm volatile("cp.async.commit_group;\n");
}
template<int N> __device__ __forceinline__ void cp_wait() {
    asm volatile("cp.async.wait_group %0;\n" :: "n"(N));
}

// ---------------- kernels ----------------
__global__ void zero_kernel(int n) {
    int i = blockIdx.x * blockDim.x + threadIdx.x;
    if (i < n) g_cnt[i] = 0;
    if (i == 0) g_flag = 0;
}

// Detect int32 vs int64 edge_index: for int64 node ids < 2^31 the high words
// are all zero; for int32 they contain random node ids.
__global__ void detect_kernel(const int* p, int E) {
    int i = blockIdx.x * blockDim.x + threadIdx.x;
    if (i < 1024 && i < E) {
        if (p[2 * i + 1] != 0) atomicOr(&g_flag, 1);
    }
}

// W_combT[k][o] = sum_m W_gat[o][m] * W_fc[m][k];  grid=(OUT_FT), block=(IN_FT)
__global__ void wcomb_kernel(const float* __restrict__ Wgat,
                             const float* __restrict__ Wfc) {
    __shared__ float wrow[OUT_FT];
    int o = blockIdx.x;
    int k = threadIdx.x;
    if (k < OUT_FT) wrow[k] = Wgat[o * OUT_FT + k];
    __syncthreads();
    float acc = 0.f;
#pragma unroll 8
    for (int m = 0; m < OUT_FT; m++)
        acc += wrow[m] * Wfc[m * IN_FT + k];
    g_wcT[k * OUT_FT + o] = acc;          // transposed store
}

// h = seq @ W_comb^T.  BM=32 x 128 x BK=32, 128 threads, 4x8 microtile,
// cp.async double-buffered smem.  Fused epilogue computes a_s/a_d.
__global__ __launch_bounds__(128, 4) void gemm_h_kernel(
        const float* __restrict__ seq,
        const float* __restrict__ att_s,
        const float* __restrict__ att_d, int n) {
    __shared__ float As[2][BM][36];      // pitch 36 floats = 144B (16B aligned rows)
    __shared__ float Bs[2][BK][OUT_FT];

    int bm  = blockIdx.x * BM;
    int tid = threadIdx.x;
    int tx  = tid & 15;          // col group
    int ty  = tid >> 4;          // 0..7 -> 4 rows each
    int r0  = ty * 4;

    auto issue = [&](int kt, int buf) {
        int k0 = kt * BK;
#pragma unroll
        for (int i = 0; i < 2; i++) {                 // A: 32x32 = 256 x 16B
            int idx = tid + i * 128;
            int r = idx >> 3, c4 = (idx & 7) << 2;
            int row = bm + r; if (row >= n) row = n - 1;
            cp16(&As[buf][r][c4], &seq[row * IN_FT + k0 + c4]);
        }
#pragma unroll
        for (int i = 0; i < 8; i++) {                 // B: 32x128 = 1024 x 16B
            int idx = tid + i * 128;
            int kk = idx >> 5, o4 = (idx & 31) << 2;
            cp16(&Bs[buf][kk][o4], &g_wcT[(k0 + kk) * OUT_FT + o4]);
        }
        cp_commit();
    };

    float acc[4][8];
#pragma unroll
    for (int i = 0; i < 4; i++)
#pragma unroll
        for (int j = 0; j < 8; j++) acc[i][j] = 0.f;

    issue(0, 0);
    issue(1, 1);

    for (int kt = 0; kt < NKT; kt++) {
        if (kt < NKT - 1) cp_wait<1>(); else cp_wait<0>();
        __syncthreads();
        int buf = kt & 1;
#pragma unroll
        for (int kk = 0; kk < BK; kk++) {
            float a[4];
#pragma unroll
            for (int i = 0; i < 4; i++) a[i] = As[buf][r0 + i][kk];
            // thread's 8 cols: {tx*4..+3} and {64+tx*4..+3} (conflict-free LDS.128)
            float4 b0 = *(const float4*)&Bs[buf][kk][tx * 4];
            float4 b1 = *(const float4*)&Bs[buf][kk][64 + tx * 4];
            float b[8] = {b0.x, b0.y, b0.z, b0.w, b1.x, b1.y, b1.z, b1.w};
#pragma unroll
            for (int i = 0; i < 4; i++)
#pragma unroll
                for (int j = 0; j < 8; j++)
                    acc[i][j] += a[i] * b[j];
        }
        __syncthreads();
        if (kt + 2 < NKT) issue(kt + 2, buf);
    }

    // epilogue: store h + fused attention logits
    float as8[8], ad8[8];
#pragma unroll
    for (int j = 0; j < 4; j++) {
        as8[j]     = att_s[tx * 4 + j];
        as8[4 + j] = att_s[64 + tx * 4 + j];
        ad8[j]     = att_d[tx * 4 + j];
        ad8[4 + j] = att_d[64 + tx * 4 + j];
    }
#pragma unroll
    for (int i = 0; i < 4; i++) {
        int row = bm + r0 + i;
        bool valid = (row < n);
        float vs = 0.f, vd = 0.f;
#pragma unroll
        for (int j = 0; j < 8; j++) { vs += acc[i][j] * as8[j]; vd += acc[i][j] * ad8[j]; }
        if (valid) {
            *(float4*)&g_h[row * OUT_FT + tx * 4]      =
                make_float4(acc[i][0], acc[i][1], acc[i][2], acc[i][3]);
            *(float4*)&g_h[row * OUT_FT + 64 + tx * 4] =
                make_float4(acc[i][4], acc[i][5], acc[i][6], acc[i][7]);
        }
#pragma unroll
        for (int o = 1; o < 16; o <<= 1) {
            vs += __shfl_xor_sync(0xffffffffu, vs, o);
            vd += __shfl_xor_sync(0xffffffffu, vd, o);
        }
        if (valid && tx == 0) { g_as[row] = vs; g_ad[row] = vd; }
    }
}

__global__ void count_kernel(const void* eidx, int E, int n) {
    int i = blockIdx.x * blockDim.x + threadIdx.x;
    int tot = E + n;
    if (i >= tot) return;
    int s, d;
    if (i < E) { int2 sd = load_edge(eidx, i, E); s = sd.x; d = sd.y; }
    else       { s = d = i - E; }
    g_src[i] = s;
    g_dst[i] = d;
    atomicAdd(&g_cnt[d], 1);
}

// Single-block exclusive scan over g_cnt -> g_rowptr / g_fill
__global__ void scan_kernel(int n) {
    __shared__ int part[1024];
    int tid  = threadIdx.x;
    int per  = (n + 1023) / 1024;
    if (per > 16) per = 16;
    int base = tid * per;
    int loc[16];
    int sum = 0;
    for (int j = 0; j < per; j++) {
        int idx = base + j;
        int v = (idx < n) ? g_cnt[idx] : 0;
        loc[j] = sum;
        sum += v;
    }
    part[tid] = sum;
    __syncthreads();
    for (int off = 1; off < 1024; off <<= 1) {
        int v = (tid >= off) ? part[tid - off] : 0;
        __syncthreads();
        part[tid] += v;
        __syncthreads();
    }
    int excl = (tid == 0) ? 0 : part[tid - 1];
    for (int j = 0; j < per; j++) {
        int idx = base + j;
        if (idx < n) {
            int rp = excl + loc[j];
            g_rowptr[idx] = rp;
            g_fill[idx]   = rp;
        }
    }
    if (tid == 1023) g_rowptr[n] = part[1023];
}

__global__ void scatter_kernel(int E, int n) {
    int i = blockIdx.x * blockDim.x + threadIdx.x;
    int tot = E + n;
    if (i >= tot) return;
    int s = g_src[i], d = g_dst[i];
    int pos = atomicAdd(&g_fill[d], 1);
    g_csr[pos] = s;
}

// One block (128 threads) per destination node: segment softmax + weighted sum.
// Fast path: all (e, src) cached in smem; warp-parallel float4 accumulation.
__global__ __launch_bounds__(128) void aggregate_kernel(
        const float* __restrict__ gat_bias,
        const float* __restrict__ bias,
        const float* __restrict__ prelu_a,
        float* __restrict__ out, int n) {
    int d = blockIdx.x;
    if (d >= n) return;
    int tid   = threadIdx.x;
    int w     = tid >> 5, lane = tid & 31;
    int start = g_rowptr[d];
    int end   = g_rowptr[d + 1];
    int deg   = end - start;
    float ad  = g_ad[d];

    __shared__ float e_sh[MAXD];
    __shared__ int   s_sh[MAXD];
    __shared__ float red[4];
    __shared__ float accsh[4][OUT_FT];

    if (deg <= MAXD) {
        // load + leaky-relu + max
        float lm = -1e30f;
        for (int i = tid; i < deg; i += 128) {
            int s = g_csr[start + i];
            float e = g_as[s] + ad;
            e = (e >= 0.f) ? e : 0.2f * e;
            s_sh[i] = s; e_sh[i] = e;
            lm = fmaxf(lm, e);
        }
#pragma unroll
        for (int o = 16; o > 0; o >>= 1)
            lm = fmaxf(lm, __shfl_xor_sync(0xffffffffu, lm, o));
        if (lane == 0) red[w] = lm;
        __syncthreads();
        float m = fmaxf(fmaxf(red[0], red[1]), fmaxf(red[2], red[3]));
        __syncthreads();

        // exp + denom
        float ls = 0.f;
        for (int i = tid; i < deg; i += 128) {
            float p = __expf(e_sh[i] - m);
            e_sh[i] = p;
            ls += p;
        }
#pragma unroll
        for (int o = 16; o > 0; o >>= 1)
            ls += __shfl_xor_sync(0xffffffffu, ls, o);
        if (lane == 0) red[w] = ls;
        __syncthreads();
        float denom = red[0] + red[1] + red[2] + red[3];

        // warp-parallel accumulation: warp w takes edges w, w+4, ...; lane = 4 features
        float4 a4 = make_float4(0.f, 0.f, 0.f, 0.f);
        for (int j = w; j < deg; j += 4) {
            float p = e_sh[j];
            const float4 hv = *(const float4*)&g_h[s_sh[j] * OUT_FT + lane * 4];
            a4.x += p * hv.x; a4.y += p * hv.y; a4.z += p * hv.z; a4.w += p * hv.w;
        }
        *(float4*)&accsh[w][lane * 4] = a4;
        __syncthreads();
        float sum = accsh[0][tid] + accsh[1][tid] + accsh[2][tid] + accsh[3][tid];

        float o_ = sum / (denom + 1e-16f) + gat_bias[tid] + bias[tid];
        float a  = prelu_a[0];
        out[d * OUT_FT + tid] = (o_ >= 0.f) ? o_ : a * o_;
    } else {
        // generic fallback: feature-per-thread, recompute path
        float lm = -1e30f;
        for (int i = start + tid; i < end; i += 128) {
            float e = g_as[g_csr[i]] + ad;
            e = (e >= 0.f) ? e : 0.2f * e;
            lm = fmaxf(lm, e);
        }
#pragma unroll
        for (int o = 16; o > 0; o >>= 1)
            lm = fmaxf(lm, __shfl_xor_sync(0xffffffffu, lm, o));
        if (lane == 0) red[w] = lm;
        __syncthreads();
        float m = fmaxf(fmaxf(red[0], red[1]), fmaxf(red[2], red[3]));
        __syncthreads();

        float ls = 0.f;
        for (int i = start + tid; i < end; i += 128) {
            float e = g_as[g_csr[i]] + ad;
            e = (e >= 0.f) ? e : 0.2f * e;
            ls += __expf(e - m);
        }
#pragma unroll
        for (int o = 16; o > 0; o >>= 1)
            ls += __shfl_xor_sync(0xffffffffu, ls, o);
        if (lane == 0) red[w] = ls;
        __syncthreads();
        float denom = red[0] + red[1] + red[2] + red[3];
        __syncthreads();

        float acc = 0.f;
        for (int c = start; c < end; c += 128) {
            int i = c + tid;
            if (i < end) {
                int s = g_csr[i];
                float e = g_as[s] + ad;
                e = (e >= 0.f) ? e : 0.2f * e;
                e_sh[tid] = __expf(e - m);
                s_sh[tid] = s;
            }
            __syncthreads();
            int len = min(128, end - c);
            for (int j = 0; j < len; j++)
                acc += e_sh[j] * g_h[s_sh[j] * OUT_FT + tid];
            __syncthreads();
        }
        float o_ = acc / (denom + 1e-16f) + gat_bias[tid] + bias[tid];
        float a  = prelu_a[0];
        out[d * OUT_FT + tid] = (o_ >= 0.f) ? o_ : a * o_;
    }
}

// ---------------- launch ----------------
extern "C" void kernel_launch(void* const* d_in, const int* in_sizes, int n_in,
                              void* d_out, int out_size) {
    const float* seq      = (const float*)d_in[0];
    const void*  eidx     = d_in[1];
    const float* Wfc      = (const float*)d_in[2];
    const float* Wgat     = (const float*)d_in[3];
    const float* att_src  = (const float*)d_in[4];
    const float* att_dst  = (const float*)d_in[5];
    const float* gat_bias = (const float*)d_in[6];
    const float* bias     = (const float*)d_in[7];
    const float* prelu_a  = (const float*)d_in[8];
    float* out = (float*)d_out;

    int n = in_sizes[0] / IN_FT;     // 10000
    int E = in_sizes[1] / 2;         // 640000
    int tot = E + n;

    zero_kernel<<<(n + 255) / 256, 256>>>(n);
    detect_kernel<<<4, 256>>>((const int*)eidx, E);
    wcomb_kernel<<<OUT_FT, IN_FT>>>(Wgat, Wfc);
    count_kernel<<<(tot + 255) / 256, 256>>>(eidx, E, n);
    gemm_h_kernel<<<(n + BM - 1) / BM, 256 / 2>>>(seq, att_src, att_dst, n);
    scan_kernel<<<1, 1024>>>(n);
    scatter_kernel<<<(tot + 255) / 256, 256>>>(E, n);
    aggregate_kernel<<<n, 128>>>(gat_bias, bias, prelu_a, out, n);
}